// round 1
// baseline (speedup 1.0000x reference)
#include <cuda_runtime.h>
#include <cuda_bf16.h>
#include <cstddef>
#include <cstdint>

#define BB   64
#define SS   2048
#define HH   256
#define NN   256
#define BSR  (BB*SS)         /* 131072 rows */
#define CHUNK 128
#define NCH  (SS/CHUNK)      /* 16 */
#define NC2  (2*NN)          /* 512 */
#define NCAND 101

// ---------------- device scratch (static allocation only) ----------------
__device__ float g_x[(size_t)BSR*HH];      // running activation  [B*S, H]
__device__ float g_h[(size_t)BSR*HH];      // LN output / s4 input
__device__ float g_t1[(size_t)BSR*HH];     // FFN intermediate
__device__ float g_v[(size_t)BSR*NC2];     // V then X (complex planes: cols 0..255 re, 256..511 im)
__device__ float g_carry[(size_t)BB*NCH*NC2];
__device__ float g_prefix[(size_t)BB*NCH*NC2];
__device__ float g_wb[HH*NC2];             // [h][2N] B-projection weight
__device__ float g_wc[NC2*HH];             // [2N][h] C-projection weight
__device__ float g_abar[NC2];              // ar[0..255], ai[256..511]
__device__ float g_aL[NC2];                // A_bar^CHUNK
__device__ float g_coef[NC2];              // (A_bar-1)/A  (indexed by h per broadcast quirk)
__device__ float g_efinal[BB*NC2];
__device__ float g_xlast[BB*HH];
__device__ float g_hlast[BB*HH];
__device__ float g_t1last[BB*HH];

// ---------------- prep kernels ----------------
__global__ void prep_coef_kernel(const float* __restrict__ lar_p,
                                 const float* __restrict__ aim_p,
                                 const float* __restrict__ lstep_p) {
    int n = threadIdx.x;
    float step = expf(lstep_p[0]);
    float Ar = -expf(lar_p[n]);
    float Ai = aim_p[n];
    float er = expf(Ar * step);
    float sn, cs; sincosf(Ai * step, &sn, &cs);
    float abr = er * cs, abi = er * sn;
    g_abar[n] = abr; g_abar[NN + n] = abi;
    // A_bar^128 via 7 complex squarings (matches scan's product numerically)
    float plr = abr, pli = abi;
    #pragma unroll
    for (int it = 0; it < 7; ++it) {
        float r2 = plr*plr - pli*pli;
        float i2 = 2.f*plr*pli;
        plr = r2; pli = i2;
    }
    g_aL[n] = plr; g_aL[NN + n] = pli;
    // coef = (A_bar - 1) / A
    float nr = abr - 1.f, ni = abi;
    float d = Ar*Ar + Ai*Ai;
    g_coef[n]      = (nr*Ar + ni*Ai) / d;
    g_coef[NN + n] = (ni*Ar - nr*Ai) / d;
}

// B_bar[n,h] = coef[h] * B[n,h]  (broadcast quirk: coef indexes H axis)
__global__ void prep_wb_kernel(const float* __restrict__ Bp) {
    int h = blockIdx.x, n = threadIdx.x;
    float Bv = Bp[(size_t)n*HH + h];
    g_wb[h*NC2 + n]      = Bv * g_coef[h];
    g_wb[h*NC2 + NN + n] = Bv * g_coef[NN + h];
}

// Wc[n][h] = Cr[h,n];  Wc[N+n][h] = -Ci[h,n]
__global__ void prep_wc_kernel(const float* __restrict__ Cp) {
    int n = blockIdx.x, h = threadIdx.x;
    g_wc[n*HH + h]        =  Cp[((size_t)h*NN + n)*2 + 0];
    g_wc[(NN + n)*HH + h] = -Cp[((size_t)h*NN + n)*2 + 1];
}

// ---------------- embedding ----------------
__global__ void embed_kernel(const int* __restrict__ seqs,
                             const float* __restrict__ emb,
                             const float* __restrict__ pos) {
    size_t i = (size_t)blockIdx.x * blockDim.x + threadIdx.x;  // float4 index
    int row = (int)(i >> 6);
    int q = (int)(i & 63);
    int sv = seqs[row];
    float4 r = make_float4(0.f, 0.f, 0.f, 0.f);
    if (sv != 0) {
        int s = row & (SS - 1);
        float4 e = ((const float4*)emb)[(size_t)sv * 64 + q];
        float4 p = ((const float4*)pos)[(size_t)s * 64 + q];
        r = make_float4(e.x + p.x, e.y + p.y, e.z + p.z, e.w + p.w);
    }
    ((float4*)g_x)[i] = r;
}

// ---------------- layernorm (1 warp / row, H=256) ----------------
__global__ void ln_kernel(const float* __restrict__ in, float* __restrict__ out,
                          const float* __restrict__ gam, const float* __restrict__ bet,
                          int rows) {
    int warp = threadIdx.x >> 5, lane = threadIdx.x & 31;
    int row = blockIdx.x * 8 + warp;
    if (row >= rows) return;
    size_t base = (size_t)row * HH + lane * 8;
    float4 a = *(const float4*)(in + base);
    float4 b = *(const float4*)(in + base + 4);
    float v[8] = {a.x, a.y, a.z, a.w, b.x, b.y, b.z, b.w};
    float s = 0.f;
    #pragma unroll
    for (int k = 0; k < 8; k++) s += v[k];
    #pragma unroll
    for (int o = 16; o; o >>= 1) s += __shfl_xor_sync(0xffffffffu, s, o);
    float mean = s * (1.f / HH);
    float q = 0.f;
    #pragma unroll
    for (int k = 0; k < 8; k++) { float d = v[k] - mean; q += d * d; }
    #pragma unroll
    for (int o = 16; o; o >>= 1) q += __shfl_xor_sync(0xffffffffu, q, o);
    float rstd = rsqrtf(q * (1.f / HH) + 1e-5f);
    float4 g1 = *(const float4*)(gam + lane*8), g2 = *(const float4*)(gam + lane*8 + 4);
    float4 c1 = *(const float4*)(bet + lane*8), c2 = *(const float4*)(bet + lane*8 + 4);
    float gg[8] = {g1.x,g1.y,g1.z,g1.w,g2.x,g2.y,g2.z,g2.w};
    float bb[8] = {c1.x,c1.y,c1.z,c1.w,c2.x,c2.y,c2.z,c2.w};
    float o8[8];
    #pragma unroll
    for (int k = 0; k < 8; k++) o8[k] = (v[k] - mean) * rstd * gg[k] + bb[k];
    *(float4*)(out + base)     = make_float4(o8[0], o8[1], o8[2], o8[3]);
    *(float4*)(out + base + 4) = make_float4(o8[4], o8[5], o8[6], o8[7]);
}

// ---------------- SGEMM: C[M,Nn] = A[M,K] @ W[K,Nn], 128x128x8, 8x8/thread ----------------
// epi: 0 plain store; 1 x += acc + D[col]*h; 2 relu(acc+bias); 3 x = (x+acc+bias)*mask
__global__ __launch_bounds__(256, 2)
void sgemm_kernel(const float* __restrict__ A, const float* __restrict__ W,
                  float* __restrict__ C, int M, int Nn, int K, int epi,
                  const float* __restrict__ aux,    // D or bias
                  const float* __restrict__ hbuf,   // epi1
                  float* __restrict__ xio,          // epi1/3
                  const int* __restrict__ seqs) {
    __shared__ float As[8][128];
    __shared__ float Bs[8][128];
    const int tid = threadIdx.x;
    const int tx = tid & 15, ty = tid >> 4;
    const int row0 = blockIdx.y * 128, col0 = blockIdx.x * 128;
    const int lr = tid >> 1, lk = (tid & 1) << 2;
    const int wr = tid >> 5, wc = (tid & 31) << 2;
    float acc[8][8];
    #pragma unroll
    for (int i = 0; i < 8; i++)
        #pragma unroll
        for (int j = 0; j < 8; j++) acc[i][j] = 0.f;
    const float* Aptr = A + (size_t)(row0 + lr) * K + lk;
    const float* Wptr = W + (size_t)wr * Nn + col0 + wc;
    for (int k0 = 0; k0 < K; k0 += 8) {
        float4 a4 = *(const float4*)(Aptr + k0);
        As[lk + 0][lr] = a4.x; As[lk + 1][lr] = a4.y;
        As[lk + 2][lr] = a4.z; As[lk + 3][lr] = a4.w;
        float4 b4 = *(const float4*)(Wptr + (size_t)k0 * Nn);
        *(float4*)&Bs[wr][wc] = b4;
        __syncthreads();
        #pragma unroll
        for (int k = 0; k < 8; k++) {
            float ar[8], br[8];
            *(float4*)(ar)     = *(const float4*)&As[k][ty * 4];
            *(float4*)(ar + 4) = *(const float4*)&As[k][64 + ty * 4];
            *(float4*)(br)     = *(const float4*)&Bs[k][tx * 4];
            *(float4*)(br + 4) = *(const float4*)&Bs[k][64 + tx * 4];
            #pragma unroll
            for (int i = 0; i < 8; i++)
                #pragma unroll
                for (int j = 0; j < 8; j++)
                    acc[i][j] = fmaf(ar[i], br[j], acc[i][j]);
        }
        __syncthreads();
    }
    #pragma unroll
    for (int i = 0; i < 8; i++) {
        int row = row0 + ((i < 4) ? (ty * 4 + i) : (64 + ty * 4 + i - 4));
        #pragma unroll
        for (int j = 0; j < 8; j++) {
            int col = col0 + ((j < 4) ? (tx * 4 + j) : (64 + tx * 4 + j - 4));
            size_t o = (size_t)row * Nn + col;
            float v = acc[i][j];
            if (epi == 0) {
                C[o] = v;
            } else if (epi == 1) {
                xio[o] = xio[o] + v + aux[col] * hbuf[o];
            } else if (epi == 2) {
                C[o] = fmaxf(v + aux[col], 0.f);
            } else {
                float m = (seqs[row] != 0) ? 1.f : 0.f;
                xio[o] = (xio[o] + v + aux[col]) * m;
            }
        }
    }
}

// ---------------- chunked scan ----------------
__global__ void scan_local_kernel(int writeX) {
    int b = blockIdx.x / NCH, c = blockIdx.x % NCH;
    int n = threadIdx.x;
    float ar = g_abar[n], ai = g_abar[NN + n];
    float xr = 0.f, xi = 0.f;
    size_t base = ((size_t)b * SS + (size_t)c * CHUNK) * NC2;
    for (int t = 0; t < CHUNK; t++) {
        float vr = g_v[base + n], vi = g_v[base + NN + n];
        float nr = fmaf(ar, xr, fmaf(-ai, xi, vr));
        float ni = fmaf(ar, xi, fmaf( ai, xr, vi));
        if (writeX) { g_v[base + n] = nr; g_v[base + NN + n] = ni; }
        xr = nr; xi = ni;
        base += NC2;
    }
    size_t co = ((size_t)b * NCH + c) * NC2;
    g_carry[co + n] = xr; g_carry[co + NN + n] = xi;
}

__global__ void scan_carry_kernel(int writeFinal) {
    int b = blockIdx.x, n = threadIdx.x;
    float alr = g_aL[n], ali = g_aL[NN + n];
    float er = 0.f, ei = 0.f;
    for (int c = 0; c < NCH; c++) {
        size_t o = ((size_t)b * NCH + c) * NC2;
        g_prefix[o + n] = er; g_prefix[o + NN + n] = ei;
        float cr = g_carry[o + n], ci = g_carry[o + NN + n];
        float tr = fmaf(alr, er, fmaf(-ali, ei, cr));
        float ti = fmaf(alr, ei, fmaf( ali, er, ci));
        er = tr; ei = ti;
    }
    if (writeFinal) { g_efinal[b * NC2 + n] = er; g_efinal[b * NC2 + NN + n] = ei; }
}

__global__ void scan_fix_kernel() {
    int b = blockIdx.x / NCH, c = blockIdx.x % NCH;
    if (c == 0) return;
    int n = threadIdx.x;
    size_t o = ((size_t)b * NCH + c) * NC2;
    float pr = g_prefix[o + n], pi = g_prefix[o + NN + n];
    float ar = g_abar[n], ai = g_abar[NN + n];
    float pwr = ar, pwi = ai;
    size_t base = ((size_t)b * SS + (size_t)c * CHUNK) * NC2;
    for (int t = 0; t < CHUNK; t++) {
        g_v[base + n]      += pwr * pr - pwi * pi;
        g_v[base + NN + n] += pwr * pi + pwi * pr;
        float nr = pwr * ar - pwi * ai;
        float ni = pwr * ai + pwi * ar;
        pwr = nr; pwi = ni;
        base += NC2;
    }
}

// ---------------- block-1 tail (final token only) ----------------
__global__ void tail_s4_kernel(const float* __restrict__ Dp) {
    int b = blockIdx.x, h = threadIdx.x;
    __shared__ float e[NC2];
    e[h]      = g_efinal[b * NC2 + h];
    e[h + HH] = g_efinal[b * NC2 + HH + h];
    __syncthreads();
    float acc = 0.f;
    #pragma unroll 4
    for (int n = 0; n < NC2; n++) acc = fmaf(e[n], g_wc[n * HH + h], acc);
    size_t o = ((size_t)b * SS + SS - 1) * HH + h;
    g_xlast[b * HH + h] = g_x[o] + acc + Dp[h] * g_h[o];
}

__global__ void tail_mm_kernel(const float* __restrict__ in, const float* __restrict__ W,
                               const float* __restrict__ bias, float* __restrict__ out,
                               int mode, const int* __restrict__ seqs) {
    int b = blockIdx.x, h = threadIdx.x;
    __shared__ float r[HH];
    r[h] = in[b * HH + h];
    __syncthreads();
    float acc = bias[h];
    #pragma unroll 4
    for (int k = 0; k < HH; k++) acc = fmaf(r[k], W[k * HH + h], acc);
    if (mode == 0) {
        out[b * HH + h] = fmaxf(acc, 0.f);
    } else {
        float m = (seqs[b * SS + SS - 1] != 0) ? 1.f : 0.f;
        out[b * HH + h] = (out[b * HH + h] + acc) * m;
    }
}

// ---------------- logits ----------------
__global__ void logits_kernel(const int* __restrict__ idxs,
                              const float* __restrict__ emb,
                              float* __restrict__ out) {
    int wg = blockIdx.x * 8 + (threadIdx.x >> 5);
    int lane = threadIdx.x & 31;
    if (wg >= BB * NCAND) return;
    int b = wg / NCAND, c = wg % NCAND;
    int id = idxs[b * NCAND + c];
    const float* xe = g_hlast + b * HH;
    const float* ce = emb + (size_t)id * HH;
    float acc = 0.f;
    #pragma unroll
    for (int k = lane; k < HH; k += 32) acc = fmaf(xe[k], ce[k], acc);
    #pragma unroll
    for (int o = 16; o; o >>= 1) acc += __shfl_xor_sync(0xffffffffu, acc, o);
    if (lane == 0) out[b * NCAND + c] = acc;
}

// ---------------- host launch ----------------
extern "C" void kernel_launch(void* const* d_in, const int* in_sizes, int n_in,
                              void* d_out, int out_size) {
    const int*   seqs     = (const int*)  d_in[0];
    const int*   idxs     = (const int*)  d_in[1];
    const float* item_emb = (const float*)d_in[2];
    const float* pos_emb  = (const float*)d_in[3];
    const float* ln_g     = (const float*)d_in[4];
    const float* ln_b     = (const float*)d_in[5];
    const float* log_A    = (const float*)d_in[6];
    const float* A_imag   = (const float*)d_in[7];
    const float* B_ssm    = (const float*)d_in[8];
    const float* C_ssm    = (const float*)d_in[9];
    const float* D_ssm    = (const float*)d_in[10];
    const float* log_step = (const float*)d_in[11];
    const float* W1       = (const float*)d_in[12];
    const float* b1       = (const float*)d_in[13];
    const float* W2       = (const float*)d_in[14];
    const float* b2       = (const float*)d_in[15];
    const float* ln_f_g   = (const float*)d_in[16];
    const float* ln_f_b   = (const float*)d_in[17];
    float* out = (float*)d_out;

    float *px, *ph, *pv, *pt1, *pwb, *pwc, *pxl, *phl, *pt1l;
    cudaGetSymbolAddress((void**)&px,   g_x);
    cudaGetSymbolAddress((void**)&ph,   g_h);
    cudaGetSymbolAddress((void**)&pv,   g_v);
    cudaGetSymbolAddress((void**)&pt1,  g_t1);
    cudaGetSymbolAddress((void**)&pwb,  g_wb);
    cudaGetSymbolAddress((void**)&pwc,  g_wc);
    cudaGetSymbolAddress((void**)&pxl,  g_xlast);
    cudaGetSymbolAddress((void**)&phl,  g_hlast);
    cudaGetSymbolAddress((void**)&pt1l, g_t1last);

    // 1. embedding + mask
    embed_kernel<<<(BSR * (HH / 4)) / 256, 256>>>(seqs, item_emb, pos_emb);

    for (int i = 0; i < 2; i++) {
        prep_coef_kernel<<<1, 256>>>(log_A + i * NN, A_imag + i * NN, log_step + i);
        prep_wb_kernel<<<HH, NN>>>(B_ssm + (size_t)i * NN * HH);
        prep_wc_kernel<<<NN, HH>>>(C_ssm + (size_t)i * HH * NN * 2);

        // h = LN(x)
        ln_kernel<<<BSR / 8, 256>>>(px, ph, ln_g + i * HH, ln_b + i * HH, BSR);
        // V = h @ Wb   [BSR,512]
        sgemm_kernel<<<dim3(NC2 / 128, BSR / 128), 256>>>(
            ph, pwb, pv, BSR, NC2, HH, 0, nullptr, nullptr, nullptr, nullptr);
        // chunked scan
        scan_local_kernel<<<BB * NCH, NN>>>(i == 0 ? 1 : 0);
        scan_carry_kernel<<<BB, NN>>>(i == 1 ? 1 : 0);

        if (i == 0) {
            scan_fix_kernel<<<BB * NCH, NN>>>();
            // x += X @ Wc + D*h
            sgemm_kernel<<<dim3(HH / 128, BSR / 128), 256>>>(
                pv, pwc, nullptr, BSR, HH, NC2, 1, D_ssm, ph, px, nullptr);
            // h2 = LN(x)  (same gamma/beta within block)
            ln_kernel<<<BSR / 8, 256>>>(px, ph, ln_g + i * HH, ln_b + i * HH, BSR);
            // t1 = relu(h2 @ W1 + b1)
            sgemm_kernel<<<dim3(HH / 128, BSR / 128), 256>>>(
                ph, W1, pt1, BSR, HH, HH, 2, b1, nullptr, nullptr, nullptr);
            // x = (x + t1 @ W2 + b2) * mask
            sgemm_kernel<<<dim3(HH / 128, BSR / 128), 256>>>(
                pt1, W2, nullptr, BSR, HH, HH, 3, b2, nullptr, px, seqs);
        } else {
            // final-token-only tail
            tail_s4_kernel<<<BB, HH>>>(D_ssm + HH);
            ln_kernel<<<8, 256>>>(pxl, phl, ln_g + HH, ln_b + HH, BB);
            tail_mm_kernel<<<BB, HH>>>(phl, W1 + HH * HH, b1 + HH, pt1l, 0, nullptr);
            tail_mm_kernel<<<BB, HH>>>(pt1l, W2 + HH * HH, b2 + HH, pxl, 1, seqs);
            ln_kernel<<<8, 256>>>(pxl, phl, ln_f_g, ln_f_b, BB);
        }
    }

    // logits
    logits_kernel<<<(BB * NCAND + 7) / 8, 256>>>(idxs, item_emb, out);
}

// round 11
// speedup vs baseline: 1.6704x; 1.6704x over previous
#include <cuda_runtime.h>
#include <cuda_bf16.h>
#include <cstddef>
#include <cstdint>

#define BB   64
#define SS   2048
#define HH   256
#define NN   256
#define BSR  (BB*SS)         /* 131072 rows */
#define CHUNK 128
#define NCH  (SS/CHUNK)      /* 16 */
#define NC2  (2*NN)          /* 512 */
#define NCAND 101

// ================= device scratch =================
__device__ float g_x[(size_t)BSR*HH];              // running activation fp32
__device__ float g_v[(size_t)BSR*NC2];             // V (complex planes: 0..255 re, 256..511 im)
__device__ __nv_bfloat16 g_hh[(size_t)BSR*HH];     // LN out hi
__device__ __nv_bfloat16 g_hl[(size_t)BSR*HH];     // LN out lo
__device__ __nv_bfloat16 g_xsh[(size_t)BSR*NC2];   // scanned X hi
__device__ __nv_bfloat16 g_xsl[(size_t)BSR*NC2];   // scanned X lo
__device__ __nv_bfloat16 g_t1h[(size_t)BSR*HH];    // FFN mid hi
__device__ __nv_bfloat16 g_t1l[(size_t)BSR*HH];    // FFN mid lo
__device__ float g_carry[(size_t)BB*NCH*NC2];
__device__ float g_prefix[(size_t)BB*NCH*NC2];
__device__ __nv_bfloat16 g_wbth[NC2*HH], g_wbtl[NC2*HH];   // Wb^T [n2][h]
__device__ __nv_bfloat16 g_wcth[HH*NC2], g_wctl[HH*NC2];   // Wc^T [h][n2]
__device__ __nv_bfloat16 g_w1th[HH*HH],  g_w1tl[HH*HH];    // W1^T [j][k]
__device__ __nv_bfloat16 g_w2th[HH*HH],  g_w2tl[HH*HH];    // W2^T [j][k]
__device__ float g_wc[NC2*HH];             // fp32 Wc for blk1 tail
__device__ float g_abar[NC2];
__device__ float g_aL[NC2];
__device__ float g_coef[NC2];
__device__ float g_efinal[BB*NC2];
__device__ float g_xlast[BB*HH];
__device__ float g_hlast[BB*HH];
__device__ float g_t1last[BB*HH];

// ================= prep kernels =================
__global__ void prep_coef_kernel(const float* __restrict__ lar_p,
                                 const float* __restrict__ aim_p,
                                 const float* __restrict__ lstep_p) {
    int n = threadIdx.x;
    float step = expf(lstep_p[0]);
    float Ar = -expf(lar_p[n]);
    float Ai = aim_p[n];
    float er = expf(Ar * step);
    float sn, cs; sincosf(Ai * step, &sn, &cs);
    float abr = er * cs, abi = er * sn;
    g_abar[n] = abr; g_abar[NN + n] = abi;
    float plr = abr, pli = abi;
    #pragma unroll
    for (int it = 0; it < 7; ++it) {
        float r2 = plr*plr - pli*pli;
        float i2 = 2.f*plr*pli;
        plr = r2; pli = i2;
    }
    g_aL[n] = plr; g_aL[NN + n] = pli;
    float nr = abr - 1.f, ni = abi;
    float d = Ar*Ar + Ai*Ai;
    g_coef[n]      = (nr*Ar + ni*Ai) / d;
    g_coef[NN + n] = (ni*Ar - nr*Ai) / d;
}

// Wb^T[n2][h] = B[n2 mod N, h] * coef[h or N+h]
__global__ void prep_wbt_kernel(const float* __restrict__ Bp) {
    int n2 = blockIdx.x, h = threadIdx.x;
    float c = g_coef[(n2 < NN) ? h : (NN + h)];
    float v = Bp[(size_t)(n2 & (NN - 1)) * HH + h] * c;
    __nv_bfloat16 hi = __float2bfloat16(v);
    g_wbth[n2 * HH + h] = hi;
    g_wbtl[n2 * HH + h] = __float2bfloat16(v - __bfloat162float(hi));
}

// Wc^T[h][n2]  (+ fp32 Wc[n2][h] for blk1 tail)
__global__ void prep_wct_kernel(const float* __restrict__ Cp) {
    int h = blockIdx.x, n2 = threadIdx.x;  // 512 threads
    float v = (n2 < NN) ? Cp[((size_t)h * NN + n2) * 2]
                        : -Cp[((size_t)h * NN + (n2 - NN)) * 2 + 1];
    g_wc[(size_t)n2 * HH + h] = v;
    __nv_bfloat16 hi = __float2bfloat16(v);
    g_wcth[(size_t)h * NC2 + n2] = hi;
    g_wctl[(size_t)h * NC2 + n2] = __float2bfloat16(v - __bfloat162float(hi));
}

// W^T[j][k] = W[k][j]
__global__ void prep_wt_kernel(const float* __restrict__ W,
                               __nv_bfloat16* __restrict__ th,
                               __nv_bfloat16* __restrict__ tl) {
    int j = blockIdx.x, k = threadIdx.x;
    float v = W[(size_t)k * HH + j];
    __nv_bfloat16 hi = __float2bfloat16(v);
    th[j * HH + k] = hi;
    tl[j * HH + k] = __float2bfloat16(v - __bfloat162float(hi));
}

// ================= embedding =================
__global__ void embed_kernel(const int* __restrict__ seqs,
                             const float* __restrict__ emb,
                             const float* __restrict__ pos) {
    size_t i = (size_t)blockIdx.x * blockDim.x + threadIdx.x;
    int row = (int)(i >> 6);
    int q = (int)(i & 63);
    int sv = seqs[row];
    float4 r = make_float4(0.f, 0.f, 0.f, 0.f);
    if (sv != 0) {
        int s = row & (SS - 1);
        float4 e = ((const float4*)emb)[(size_t)sv * 64 + q];
        float4 p = ((const float4*)pos)[(size_t)s * 64 + q];
        r = make_float4(e.x + p.x, e.y + p.y, e.z + p.z, e.w + p.w);
    }
    ((float4*)g_x)[i] = r;
}

// ================= layernorm =================
__device__ __forceinline__ void ln_core(const float* in, size_t base, int lane,
                                        const float* gam, const float* bet, float* o8) {
    float4 a = *(const float4*)(in + base);
    float4 b = *(const float4*)(in + base + 4);
    float v[8] = {a.x, a.y, a.z, a.w, b.x, b.y, b.z, b.w};
    float s = 0.f;
    #pragma unroll
    for (int k = 0; k < 8; k++) s += v[k];
    #pragma unroll
    for (int o = 16; o; o >>= 1) s += __shfl_xor_sync(0xffffffffu, s, o);
    float mean = s * (1.f / HH);
    float q = 0.f;
    #pragma unroll
    for (int k = 0; k < 8; k++) { float d = v[k] - mean; q += d * d; }
    #pragma unroll
    for (int o = 16; o; o >>= 1) q += __shfl_xor_sync(0xffffffffu, q, o);
    float rstd = rsqrtf(q * (1.f / HH) + 1e-5f);
    float4 g1 = *(const float4*)(gam + lane*8), g2 = *(const float4*)(gam + lane*8 + 4);
    float4 c1 = *(const float4*)(bet + lane*8), c2 = *(const float4*)(bet + lane*8 + 4);
    float gg[8] = {g1.x,g1.y,g1.z,g1.w,g2.x,g2.y,g2.z,g2.w};
    float bb[8] = {c1.x,c1.y,c1.z,c1.w,c2.x,c2.y,c2.z,c2.w};
    #pragma unroll
    for (int k = 0; k < 8; k++) o8[k] = (v[k] - mean) * rstd * gg[k] + bb[k];
}

__global__ void ln_kernel(const float* __restrict__ in, float* __restrict__ out,
                          const float* __restrict__ gam, const float* __restrict__ bet,
                          int rows) {
    int warp = threadIdx.x >> 5, lane = threadIdx.x & 31;
    int row = blockIdx.x * 8 + warp;
    if (row >= rows) return;
    size_t base = (size_t)row * HH + lane * 8;
    float o8[8];
    ln_core(in, base, lane, gam, bet, o8);
    *(float4*)(out + base)     = make_float4(o8[0], o8[1], o8[2], o8[3]);
    *(float4*)(out + base + 4) = make_float4(o8[4], o8[5], o8[6], o8[7]);
}

__global__ void ln_split_kernel(const float* __restrict__ in,
                                __nv_bfloat16* __restrict__ oh,
                                __nv_bfloat16* __restrict__ ol,
                                const float* __restrict__ gam,
                                const float* __restrict__ bet) {
    int warp = threadIdx.x >> 5, lane = threadIdx.x & 31;
    int row = blockIdx.x * 8 + warp;
    size_t base = (size_t)row * HH + lane * 8;
    float o8[8];
    ln_core(in, base, lane, gam, bet, o8);
    uint32_t hw[4], lw[4];
    #pragma unroll
    for (int k = 0; k < 4; k++) {
        float a = o8[2*k], b = o8[2*k+1];
        __nv_bfloat16 ah = __float2bfloat16(a), bh = __float2bfloat16(b);
        __nv_bfloat16 al = __float2bfloat16(a - __bfloat162float(ah));
        __nv_bfloat16 bl = __float2bfloat16(b - __bfloat162float(bh));
        __nv_bfloat162 hv; hv.x = ah; hv.y = bh;
        __nv_bfloat162 lv; lv.x = al; lv.y = bl;
        hw[k] = *(uint32_t*)&hv; lw[k] = *(uint32_t*)&lv;
    }
    *(uint4*)(oh + base) = make_uint4(hw[0], hw[1], hw[2], hw[3]);
    *(uint4*)(ol + base) = make_uint4(lw[0], lw[1], lw[2], lw[3]);
}

// ================= mma.sync split-bf16 GEMM (base ISA, no tcgen05) =================
// C[M,Nn] = A[M,K] @ Bt[Nn,K]^T with A = Ah+Al, B = Bh+Bl (3 products).
// CTA 128x128, 512 threads = 16 warps (4x4), warp tile 32x32 (m16n8k16).
// epi: 0 store fp32 C; 1 x += acc + aux*(hh+hl); 2 relu(acc+aux)->t1 planes; 3 x=(x+acc+aux)*mask
#define Bb  128
#define KC  64
#define LDT 72                       /* padded smem row stride (bf16) */
#define TILE_B (128*LDT*2)           /* 18432 bytes per plane tile */
#define MG_SMEM (4*TILE_B)           /* 73728 bytes */

__device__ __forceinline__ uint32_t smem_u32(const void* p) {
    uint32_t a;
    asm("{ .reg .u64 t; cvta.to.shared.u64 t, %1; cvt.u32.u64 %0, t; }" : "=r"(a) : "l"(p));
    return a;
}

#define LDSM_X4(r0,r1,r2,r3,addr) \
    asm volatile("ldmatrix.sync.aligned.m8n8.x4.shared.b16 {%0,%1,%2,%3}, [%4];" \
        : "=r"(r0),"=r"(r1),"=r"(r2),"=r"(r3) : "r"(addr))
#define LDSM_X2(r0,r1,addr) \
    asm volatile("ldmatrix.sync.aligned.m8n8.x2.shared.b16 {%0,%1}, [%2];" \
        : "=r"(r0),"=r"(r1) : "r"(addr))
#define MMA_BF16(c0,c1,c2,c3,a0,a1,a2,a3,b0,b1) \
    asm volatile("mma.sync.aligned.m16n8k16.row.col.f32.bf16.bf16.f32 " \
        "{%0,%1,%2,%3}, {%4,%5,%6,%7}, {%8,%9}, {%0,%1,%2,%3};" \
        : "+f"(c0),"+f"(c1),"+f"(c2),"+f"(c3) \
        : "r"(a0),"r"(a1),"r"(a2),"r"(a3),"r"(b0),"r"(b1))

__global__ __launch_bounds__(512, 1)
void mgemm_kernel(const __nv_bfloat16* __restrict__ Ah, const __nv_bfloat16* __restrict__ Al,
                  const __nv_bfloat16* __restrict__ Bh, const __nv_bfloat16* __restrict__ Bl,
                  float* __restrict__ Cout, int Nn, int K, int epi,
                  const float* __restrict__ aux,
                  const __nv_bfloat16* __restrict__ hhp, const __nv_bfloat16* __restrict__ hlp,
                  float* __restrict__ xio,
                  __nv_bfloat16* __restrict__ t1h, __nv_bfloat16* __restrict__ t1l,
                  const int* __restrict__ seqs) {
    extern __shared__ char smem[];
    const int tid  = threadIdx.x;
    const int wid  = tid >> 5;
    const int lane = tid & 31;
    const int warp_m = wid >> 2;          // 0..3
    const int warp_n = wid & 3;           // 0..3
    const int row0 = blockIdx.y * 128;
    const int n0   = blockIdx.x * Bb;

    const uint32_t sA[2] = { smem_u32(smem),            smem_u32(smem + TILE_B) };
    const uint32_t sB[2] = { smem_u32(smem + 2*TILE_B), smem_u32(smem + 3*TILE_B) };
    const __nv_bfloat16* gsrc[4] = { Ah, Al, Bh, Bl };

    float c[2][4][4];
    #pragma unroll
    for (int mt = 0; mt < 2; mt++)
        #pragma unroll
        for (int nt = 0; nt < 4; nt++)
            #pragma unroll
            for (int q = 0; q < 4; q++) c[mt][nt][q] = 0.f;

    // ldmatrix smem addresses (byte offsets within a plane tile), fixed per lane
    // A x4: row = (lane&15), col-half = (lane>>4)*8
    const uint32_t a_off = (uint32_t)((lane & 15) * (LDT*2) + ((lane >> 4) << 3) * 2);
    // B x2 (non-trans): lanes 0-7 rows n0..+7 at k, lanes 8-15 same rows at k+8
    const uint32_t b_off = (uint32_t)((lane & 7) * (LDT*2) + (((lane >> 3) & 1) << 3) * 2);

    const int nchunks = K >> 6;
    for (int ch = 0; ch < nchunks; ch++) {
        if (ch > 0) __syncthreads();
        // ---- load chunk (4 tiles x 1024 uint4) ----
        const int k0 = ch << 6;
        #pragma unroll
        for (int it = 0; it < 8; it++) {
            int i = tid + it * 512;
            int t = i >> 10, j = i & 1023;
            int row = j >> 3, seg = j & 7;
            int grow = (t < 2) ? (row0 + row) : (n0 + row);
            uint4 v = *(const uint4*)(gsrc[t] + (size_t)grow * K + k0 + seg * 8);
            *(uint4*)(smem + t * TILE_B + row * (LDT*2) + seg * 16) = v;
        }
        __syncthreads();
        // ---- compute: 4 k16-steps, 3 products each ----
        #pragma unroll
        for (int ks = 0; ks < 4; ks++) {
            const uint32_t kb = (uint32_t)(ks * 16 * 2);
            uint32_t af[2][2][4];   // [plane][mt][4]
            uint32_t bf[2][4][2];   // [plane][nt][2]
            #pragma unroll
            for (int p = 0; p < 2; p++)
                #pragma unroll
                for (int mt = 0; mt < 2; mt++) {
                    uint32_t addr = sA[p] + (uint32_t)((warp_m*32 + mt*16) * (LDT*2)) + kb + a_off;
                    LDSM_X4(af[p][mt][0], af[p][mt][1], af[p][mt][2], af[p][mt][3], addr);
                }
            #pragma unroll
            for (int p = 0; p < 2; p++)
                #pragma unroll
                for (int nt = 0; nt < 4; nt++) {
                    uint32_t addr = sB[p] + (uint32_t)((warp_n*32 + nt*8) * (LDT*2)) + kb + b_off;
                    LDSM_X2(bf[p][nt][0], bf[p][nt][1], addr);
                }
            #pragma unroll
            for (int mt = 0; mt < 2; mt++)
                #pragma unroll
                for (int nt = 0; nt < 4; nt++) {
                    MMA_BF16(c[mt][nt][0], c[mt][nt][1], c[mt][nt][2], c[mt][nt][3],
                             af[0][mt][0], af[0][mt][1], af[0][mt][2], af[0][mt][3],
                             bf[0][nt][0], bf[0][nt][1]);
                    MMA_BF16(c[mt][nt][0], c[mt][nt][1], c[mt][nt][2], c[mt][nt][3],
                             af[0][mt][0], af[0][mt][1], af[0][mt][2], af[0][mt][3],
                             bf[1][nt][0], bf[1][nt][1]);
                    MMA_BF16(c[mt][nt][0], c[mt][nt][1], c[mt][nt][2], c[mt][nt][3],
                             af[1][mt][0], af[1][mt][1], af[1][mt][2], af[1][mt][3],
                             bf[0][nt][0], bf[0][nt][1]);
                }
        }
    }

    // ---- epilogue ----
    const int gid = lane >> 2, tg = lane & 3;
    #pragma unroll
    for (int mt = 0; mt < 2; mt++) {
        int r[2];
        r[0] = row0 + warp_m*32 + mt*16 + gid;
        r[1] = r[0] + 8;
        #pragma unroll
        for (int half = 0; half < 2; half++) {
            int row = r[half];
            #pragma unroll
            for (int nt = 0; nt < 4; nt++) {
                int col = n0 + warp_n*32 + nt*8 + tg*2;
                float v0 = c[mt][nt][half*2], v1 = c[mt][nt][half*2 + 1];
                if (epi == 0) {
                    *(float2*)(Cout + (size_t)row * Nn + col) = make_float2(v0, v1);
                } else if (epi == 1) {
                    size_t o = (size_t)row * HH + col;
                    float2 xv = *(float2*)(xio + o);
                    float2 h = __bfloat1622float2(*(const __nv_bfloat162*)(hhp + o));
                    float2 l = __bfloat1622float2(*(const __nv_bfloat162*)(hlp + o));
                    xv.x += v0 + aux[col]   * (h.x + l.x);
                    xv.y += v1 + aux[col+1] * (h.y + l.y);
                    *(float2*)(xio + o) = xv;
                } else if (epi == 2) {
                    size_t o = (size_t)row * HH + col;
                    float a = fmaxf(v0 + aux[col],   0.f);
                    float b = fmaxf(v1 + aux[col+1], 0.f);
                    __nv_bfloat16 ah2 = __float2bfloat16(a), bh2 = __float2bfloat16(b);
                    __nv_bfloat16 al2 = __float2bfloat16(a - __bfloat162float(ah2));
                    __nv_bfloat16 bl2 = __float2bfloat16(b - __bfloat162float(bh2));
                    __nv_bfloat162 hv; hv.x = ah2; hv.y = bh2;
                    __nv_bfloat162 lv; lv.x = al2; lv.y = bl2;
                    *(__nv_bfloat162*)(t1h + o) = hv;
                    *(__nv_bfloat162*)(t1l + o) = lv;
                } else {
                    float m = (seqs[row] != 0) ? 1.f : 0.f;
                    size_t o = (size_t)row * HH + col;
                    float2 xv = *(float2*)(xio + o);
                    xv.x = (xv.x + v0 + aux[col])   * m;
                    xv.y = (xv.y + v1 + aux[col+1]) * m;
                    *(float2*)(xio + o) = xv;
                }
            }
        }
    }
}

// ================= chunked scan =================
// Pass 1: carry-only local scan (no X writeback).
__global__ void scan_local_kernel() {
    int b = blockIdx.x / NCH, c = blockIdx.x % NCH;
    int n = threadIdx.x;
    float ar = g_abar[n], ai = g_abar[NN + n];
    float xr = 0.f, xi = 0.f;
    size_t base = ((size_t)b * SS + (size_t)c * CHUNK) * NC2;
    for (int t = 0; t < CHUNK; t++) {
        float vr = g_v[base + n], vi = g_v[base + NN + n];
        float nr = fmaf(ar, xr, fmaf(-ai, xi, vr));
        float ni = fmaf(ar, xi, fmaf( ai, xr, vi));
        xr = nr; xi = ni;
        base += NC2;
    }
    size_t co = ((size_t)b * NCH + c) * NC2;
    g_carry[co + n] = xr; g_carry[co + NN + n] = xi;
}

__global__ void scan_carry_kernel(int writeFinal) {
    int b = blockIdx.x, n = threadIdx.x;
    float alr = g_aL[n], ali = g_aL[NN + n];
    float er = 0.f, ei = 0.f;
    for (int c = 0; c < NCH; c++) {
        size_t o = ((size_t)b * NCH + c) * NC2;
        g_prefix[o + n] = er; g_prefix[o + NN + n] = ei;
        float cr = g_carry[o + n], ci = g_carry[o + NN + n];
        float tr = fmaf(alr, er, fmaf(-ali, ei, cr));
        float ti = fmaf(alr, ei, fmaf( ali, er, ci));
        er = tr; ei = ti;
    }
    if (writeFinal) { g_efinal[b * NC2 + n] = er; g_efinal[b * NC2 + NN + n] = ei; }
}

// Pass 2: full scan seeded with chunk-entry state (prefix), emit bf16 hi/lo planes.
__global__ void scan_finalize_kernel() {
    int b = blockIdx.x / NCH, c = blockIdx.x % NCH;
    int n = threadIdx.x;
    size_t po = ((size_t)b * NCH + c) * NC2;
    float xr = g_prefix[po + n], xi = g_prefix[po + NN + n];
    float ar = g_abar[n], ai = g_abar[NN + n];
    size_t base = ((size_t)b * SS + (size_t)c * CHUNK) * NC2;
    for (int t = 0; t < CHUNK; t++) {
        float vr = g_v[base + n], vi = g_v[base + NN + n];
        float nr = fmaf(ar, xr, fmaf(-ai, xi, vr));
        float ni = fmaf(ar, xi, fmaf( ai, xr, vi));
        xr = nr; xi = ni;
        __nv_bfloat16 rh = __float2bfloat16(xr);
        __nv_bfloat16 ih = __float2bfloat16(xi);
        g_xsh[base + n]      = rh;
        g_xsl[base + n]      = __float2bfloat16(xr - __bfloat162float(rh));
        g_xsh[base + NN + n] = ih;
        g_xsl[base + NN + n] = __float2bfloat16(xi - __bfloat162float(ih));
        base += NC2;
    }
}

// ================= block-1 tail (final token only) =================
__global__ void tail_s4_kernel(const float* __restrict__ Dp) {
    int b = blockIdx.x, h = threadIdx.x;
    __shared__ float e[NC2];
    e[h]      = g_efinal[b * NC2 + h];
    e[h + HH] = g_efinal[b * NC2 + HH + h];
    __syncthreads();
    float acc = 0.f;
    #pragma unroll 4
    for (int n = 0; n < NC2; n++) acc = fmaf(e[n], g_wc[n * HH + h], acc);
    size_t o = ((size_t)b * SS + SS - 1) * HH + h;
    float hv = __bfloat162float(g_hh[o]) + __bfloat162float(g_hl[o]);
    g_xlast[b * HH + h] = g_x[o] + acc + Dp[h] * hv;
}

__global__ void tail_mm_kernel(const float* __restrict__ in, const float* __restrict__ W,
                               const float* __restrict__ bias, float* __restrict__ out,
                               int mode, const int* __restrict__ seqs) {
    int b = blockIdx.x, h = threadIdx.x;
    __shared__ float r[HH];
    r[h] = in[b * HH + h];
    __syncthreads();
    float acc = bias[h];
    #pragma unroll 4
    for (int k = 0; k < HH; k++) acc = fmaf(r[k], W[k * HH + h], acc);
    if (mode == 0) {
        out[b * HH + h] = fmaxf(acc, 0.f);
    } else {
        float m = (seqs[b * SS + SS - 1] != 0) ? 1.f : 0.f;
        out[b * HH + h] = (out[b * HH + h] + acc) * m;
    }
}

// ================= logits =================
__global__ void logits_kernel(const int* __restrict__ idxs,
                              const float* __restrict__ emb,
                              float* __restrict__ out) {
    int wg = blockIdx.x * 8 + (threadIdx.x >> 5);
    int lane = threadIdx.x & 31;
    if (wg >= BB * NCAND) return;
    int b = wg / NCAND, c = wg % NCAND;
    int id = idxs[b * NCAND + c];
    const float* xe = g_hlast + b * HH;
    const float* ce = emb + (size_t)id * HH;
    float acc = 0.f;
    #pragma unroll
    for (int k = lane; k < HH; k += 32) acc = fmaf(xe[k], ce[k], acc);
    #pragma unroll
    for (int o = 16; o; o >>= 1) acc += __shfl_xor_sync(0xffffffffu, acc, o);
    if (lane == 0) out[b * NCAND + c] = acc;
}

// ================= host launch =================
extern "C" void kernel_launch(void* const* d_in, const int* in_sizes, int n_in,
                              void* d_out, int out_size) {
    const int*   seqs     = (const int*)  d_in[0];
    const int*   idxs     = (const int*)  d_in[1];
    const float* item_emb = (const float*)d_in[2];
    const float* pos_emb  = (const float*)d_in[3];
    const float* ln_g     = (const float*)d_in[4];
    const float* ln_b     = (const float*)d_in[5];
    const float* log_A    = (const float*)d_in[6];
    const float* A_imag   = (const float*)d_in[7];
    const float* B_ssm    = (const float*)d_in[8];
    const float* C_ssm    = (const float*)d_in[9];
    const float* D_ssm    = (const float*)d_in[10];
    const float* log_step = (const float*)d_in[11];
    const float* W1       = (const float*)d_in[12];
    const float* b1       = (const float*)d_in[13];
    const float* W2       = (const float*)d_in[14];
    const float* b2       = (const float*)d_in[15];
    const float* ln_f_g   = (const float*)d_in[16];
    const float* ln_f_b   = (const float*)d_in[17];
    float* out = (float*)d_out;

    float *px, *pv, *pxl, *phl_f, *pt1l_f;
    __nv_bfloat16 *phh, *phl, *pxsh, *pxsl, *pt1h, *pt1l;
    __nv_bfloat16 *pwbh, *pwbl, *pwch, *pwcl, *pw1h, *pw1l, *pw2h, *pw2l;
    cudaGetSymbolAddress((void**)&px,   g_x);
    cudaGetSymbolAddress((void**)&pv,   g_v);
    cudaGetSymbolAddress((void**)&phh,  g_hh);
    cudaGetSymbolAddress((void**)&phl,  g_hl);
    cudaGetSymbolAddress((void**)&pxsh, g_xsh);
    cudaGetSymbolAddress((void**)&pxsl, g_xsl);
    cudaGetSymbolAddress((void**)&pt1h, g_t1h);
    cudaGetSymbolAddress((void**)&pt1l, g_t1l);
    cudaGetSymbolAddress((void**)&pwbh, g_wbth);
    cudaGetSymbolAddress((void**)&pwbl, g_wbtl);
    cudaGetSymbolAddress((void**)&pwch, g_wcth);
    cudaGetSymbolAddress((void**)&pwcl, g_wctl);
    cudaGetSymbolAddress((void**)&pw1h, g_w1th);
    cudaGetSymbolAddress((void**)&pw1l, g_w1tl);
    cudaGetSymbolAddress((void**)&pw2h, g_w2th);
    cudaGetSymbolAddress((void**)&pw2l, g_w2tl);
    cudaGetSymbolAddress((void**)&pxl,    g_xlast);
    cudaGetSymbolAddress((void**)&phl_f,  g_hlast);
    cudaGetSymbolAddress((void**)&pt1l_f, g_t1last);

    cudaFuncSetAttribute(mgemm_kernel, cudaFuncAttributeMaxDynamicSharedMemorySize, MG_SMEM);

    embed_kernel<<<(BSR * (HH / 4)) / 256, 256>>>(seqs, item_emb, pos_emb);
    prep_wt_kernel<<<HH, HH>>>(W1, pw1h, pw1l);
    prep_wt_kernel<<<HH, HH>>>(W2, pw2h, pw2l);

    for (int i = 0; i < 2; i++) {
        prep_coef_kernel<<<1, 256>>>(log_A + i * NN, A_imag + i * NN, log_step + i);
        prep_wbt_kernel<<<NC2, HH>>>(B_ssm + (size_t)i * NN * HH);
        prep_wct_kernel<<<HH, NC2>>>(C_ssm + (size_t)i * HH * NN * 2);

        // h = LN(x)  ->  hi/lo planes
        ln_split_kernel<<<BSR / 8, 256>>>(px, phh, phl, ln_g + i * HH, ln_b + i * HH);
        // V = h @ Wb^T   [BSR,512]
        mgemm_kernel<<<dim3(NC2 / Bb, BSR / 128), 512, MG_SMEM>>>(
            phh, phl, pwbh, pwbl, pv, NC2, HH, 0,
            nullptr, nullptr, nullptr, nullptr, nullptr, nullptr, nullptr);
        // chunked scan (carry-only pass 1)
        scan_local_kernel<<<BB * NCH, NN>>>();
        scan_carry_kernel<<<BB, NN>>>(i == 1 ? 1 : 0);

        if (i == 0) {
            scan_finalize_kernel<<<BB * NCH, NN>>>();
            // x += X @ Wc^T + D*h
            mgemm_kernel<<<dim3(HH / Bb, BSR / 128), 512, MG_SMEM>>>(
                pxsh, pxsl, pwch, pwcl, nullptr, HH, NC2, 1,
                D_ssm, phh, phl, px, nullptr, nullptr, nullptr);
            // h2 = LN(x)
            ln_split_kernel<<<BSR / 8, 256>>>(px, phh, phl, ln_g + i * HH, ln_b + i * HH);
            // t1 = relu(h2 @ W1 + b1)
            mgemm_kernel<<<dim3(HH / Bb, BSR / 128), 512, MG_SMEM>>>(
                phh, phl, pw1h, pw1l, nullptr, HH, HH, 2,
                b1, nullptr, nullptr, nullptr, pt1h, pt1l, nullptr);
            // x = (x + t1 @ W2 + b2) * mask
            mgemm_kernel<<<dim3(HH / Bb, BSR / 128), 512, MG_SMEM>>>(
                pt1h, pt1l, pw2h, pw2l, nullptr, HH, HH, 3,
                b2, nullptr, nullptr, px, nullptr, nullptr, seqs);
        } else {
            tail_s4_kernel<<<BB, HH>>>(D_ssm + HH);
            ln_kernel<<<8, 256>>>(pxl, phl_f, ln_g + HH, ln_b + HH, BB);
            tail_mm_kernel<<<BB, HH>>>(phl_f, W1 + HH * HH, b1 + HH, pt1l_f, 0, nullptr);
            tail_mm_kernel<<<BB, HH>>>(pt1l_f, W2 + HH * HH, b2 + HH, pxl, 1, seqs);
            ln_kernel<<<8, 256>>>(pxl, phl_f, ln_f_g, ln_f_b, BB);
        }
    }

    logits_kernel<<<(BB * NCAND + 7) / 8, 256>>>(idxs, item_emb, out);
}